// round 8
// baseline (speedup 1.0000x reference)
#include <cuda_runtime.h>
#include <cuda_fp16.h>
#include <cstdint>

// ExtractorMLP: per-edge MLP 128->256->64->1 with per-graph instance norm.
// R8: gemm2 -> fp16 2-term split (A=Ahi+Alo, B single fp16) + double-buffered
//     software pipeline (M=64 tiles, gather(t+1) overlaps mma(t)).

#define E_EDGES 1000000
#define EP      1000064   // multiple of 128
#define NG      512
#define NN      50000
#define C1      256
#define C2      64
#define EPS_IN  1e-5f
#define NT2     (EP / 64)    // 15626
#define PGRID   148
#define TPC     ((NT2 + PGRID - 1) / PGRID)   // 106

typedef unsigned long long ull;
typedef unsigned int u32;

// ---------------- scratch ----------------
__device__ float g_Y[(size_t)NN * 512];
__device__ float g_x2[(size_t)EP * C2];
__device__ int   g_perm[EP];
__device__ int   g_gid[EP];
__device__ int   g_scol[EP];
__device__ int   g_srow[EP];
__device__ int   g_cnt[NG];
__device__ int   g_off[NG + 1];
__device__ int   g_cur[NG];
__device__ float g_inv1 [NG * C1];
__device__ float g_miv1 [NG * C1];
__device__ float g_inv2 [NG * C2];
__device__ float g_miv2 [NG * C2];
// W2 fp16 in mma-fragment-direct order (dense, 64 u32/atom; ni 8 x ki 16)
__device__ u32 g_B2h[8192];

// ---------------- helpers ----------------
__device__ __forceinline__ ull pack2(float x, float y) {
    ull r; asm("mov.b64 %0, {%1, %2};" : "=l"(r) : "f"(x), "f"(y)); return r;
}
__device__ __forceinline__ void unpack2(ull v, float& x, float& y) {
    asm("mov.b64 {%0, %1}, %2;" : "=f"(x), "=f"(y) : "l"(v));
}
__device__ __forceinline__ void fma2(ull& d, ull a, ull b) {
    asm("fma.rn.f32x2 %0, %1, %2, %0;" : "+l"(d) : "l"(a), "l"(b));
}
__device__ __forceinline__ void hsplit(float x, float y, u32& h, u32& l) {
    __half2 hh = __floats2half2_rn(x, y);
    float hx = __low2float(hh);
    float hy = __high2float(hh);
    __half2 ll = __floats2half2_rn(x - hx, y - hy);
    h = *reinterpret_cast<u32*>(&hh);
    l = *reinterpret_cast<u32*>(&ll);
}
__device__ __forceinline__ void mma_f16(float* d, const u32* a, const u32* b) {
    asm volatile(
        "mma.sync.aligned.m16n8k16.row.col.f32.f16.f16.f32 "
        "{%0,%1,%2,%3}, {%4,%5,%6,%7}, {%8,%9}, {%0,%1,%2,%3};"
        : "+f"(d[0]), "+f"(d[1]), "+f"(d[2]), "+f"(d[3])
        : "r"(a[0]), "r"(a[1]), "r"(a[2]), "r"(a[3]), "r"(b[0]), "r"(b[1]));
}
__device__ __forceinline__ void ldm_x4(u32* r, u32 addr) {
    asm volatile("ldmatrix.sync.aligned.m8n8.x4.shared.b16 {%0,%1,%2,%3}, [%4];"
        : "=r"(r[0]), "=r"(r[1]), "=r"(r[2]), "=r"(r[3]) : "r"(addr));
}
__device__ __forceinline__ u32 smem_u32(const void* p) {
    u32 a;
    asm("{ .reg .u64 t; cvta.to.shared.u64 t, %1; cvt.u32.u64 %0, t; }"
        : "=r"(a) : "l"(p));
    return a;
}

// ---------------- init ----------------
__global__ void k_zero() {
    int t = threadIdx.x;
    if (t < NG) g_cnt[t] = 0;
    if (t < (EP - E_EDGES)) {
        g_gid[E_EDGES + t] = 0;
        g_perm[E_EDGES + t] = 0;
        g_scol[E_EDGES + t] = 0;
        g_srow[E_EDGES + t] = 0;
    }
}

// W2 [256,64] -> mma B fragments, single fp16
__global__ void k_prep2(const float* __restrict__ W2) {
    int idx = blockIdx.x * blockDim.x + threadIdx.x;
    if (idx >= 8192) return;
    int a = idx >> 6, l = (idx >> 1) & 31, r = idx & 1;
    int ng = a >> 4, ki = a & 15;
    int k = ki * 16 + (l & 3) * 2 + r * 8;
    int n = ng * 8 + (l >> 2);
    __half2 h = __floats2half2_rn(W2[k * 64 + n], W2[(k + 1) * 64 + n]);
    g_B2h[idx] = *reinterpret_cast<u32*>(&h);
}

// ---------------- sort pipeline ----------------
__global__ void k_hist(const int* __restrict__ col, const int* __restrict__ batch) {
    __shared__ int h[NG];
    int t = threadIdx.x;
    for (int g = t; g < NG; g += blockDim.x) h[g] = 0;
    __syncthreads();
    int idx = blockIdx.x * blockDim.x + t;
    int stride = gridDim.x * blockDim.x;
    for (int e = idx; e < E_EDGES; e += stride)
        atomicAdd(&h[batch[col[e]]], 1);
    __syncthreads();
    for (int g = t; g < NG; g += blockDim.x)
        if (h[g]) atomicAdd(&g_cnt[g], h[g]);
}

__global__ void k_scan() {
    __shared__ int s[NG];
    int t = threadIdx.x;
    int c = g_cnt[t];
    s[t] = c;
    __syncthreads();
    for (int o = 1; o < NG; o <<= 1) {
        int v = (t >= o) ? s[t - o] : 0;
        __syncthreads();
        s[t] += v;
        __syncthreads();
    }
    int excl = s[t] - c;
    g_off[t] = excl;
    g_cur[t] = excl;
    if (t == NG - 1) g_off[NG] = s[t];
}

__global__ void k_scatter(const int* __restrict__ col, const int* __restrict__ row,
                          const int* __restrict__ batch) {
    __shared__ int sg[2048];
    __shared__ int hist[NG], base_[NG], cnt2[NG];
    int t = threadIdx.x;
    for (int g = t; g < NG; g += 256) { hist[g] = 0; cnt2[g] = 0; }
    __syncthreads();
    int e0 = blockIdx.x * 2048;
    #pragma unroll
    for (int j = 0; j < 8; j++) {
        int e = e0 + t + j * 256;
        int g = -1;
        if (e < E_EDGES) { g = batch[col[e]]; atomicAdd(&hist[g], 1); }
        sg[t + j * 256] = g;
    }
    __syncthreads();
    for (int g = t; g < NG; g += 256)
        if (hist[g]) base_[g] = atomicAdd(&g_cur[g], hist[g]);
    __syncthreads();
    #pragma unroll
    for (int j = 0; j < 8; j++) {
        int e = e0 + t + j * 256;
        if (e < E_EDGES) {
            int g = sg[t + j * 256];
            int l = atomicAdd(&cnt2[g], 1);
            int p = base_[g] + l;
            g_perm[p] = e;
            g_gid[p] = g;
            g_scol[p] = col[e];
            g_srow[p] = row[e];
        }
    }
}

// ---------------- Y = emb @ [W1top | W1bot] ----------------
__global__ __launch_bounds__(256) void k_emb(const float* __restrict__ emb,
                                             const float* __restrict__ W1)
{
    __shared__ float sE[64][66];
    __shared__ float sW[64][128];
    int nb = blockIdx.x * 64;
    int cb = blockIdx.y * 128;
    int tid = threadIdx.x;

    for (int i = tid; i < 64 * 16; i += 256) {
        int node = i >> 4, f4 = i & 15;
        float4 v = make_float4(0.f, 0.f, 0.f, 0.f);
        if (nb + node < NN)
            v = ((const float4*)emb)[(size_t)(nb + node) * 16 + f4];
        int k = f4 * 4;
        sE[k    ][node] = v.x;
        sE[k + 1][node] = v.y;
        sE[k + 2][node] = v.z;
        sE[k + 3][node] = v.w;
    }
    const float* Wsrc = (cb < 256) ? (W1 + cb) : (W1 + 64 * 256 + (cb - 256));
    for (int i = tid; i < 2048; i += 256) {
        int k = i >> 5, c4 = i & 31;
        ((float4*)sW[k])[c4] = ((const float4*)(Wsrc + (size_t)k * 256))[c4];
    }
    __syncthreads();

    int tn = tid >> 4, tc = tid & 15;
    ull acc[2][8];
    #pragma unroll
    for (int p = 0; p < 2; p++)
        #pragma unroll
        for (int j = 0; j < 8; j++) acc[p][j] = 0ull;

    #pragma unroll 8
    for (int k = 0; k < 64; k++) {
        ull p0 = *(const ull*)&sE[k][tn * 4];
        ull p1 = *(const ull*)&sE[k][tn * 4 + 2];
        float4 b0 = *(const float4*)&sW[k][tc * 8];
        float4 b1 = *(const float4*)&sW[k][tc * 8 + 4];
        float bs[8] = {b0.x, b0.y, b0.z, b0.w, b1.x, b1.y, b1.z, b1.w};
        #pragma unroll
        for (int j = 0; j < 8; j++) {
            ull bb = pack2(bs[j], bs[j]);
            fma2(acc[0][j], p0, bb);
            fma2(acc[1][j], p1, bb);
        }
    }
    #pragma unroll
    for (int p = 0; p < 2; p++) {
        float lo[8], hi[8];
        #pragma unroll
        for (int j = 0; j < 8; j++) unpack2(acc[p][j], lo[j], hi[j]);
        int n0 = nb + tn * 4 + 2 * p;
        if (n0 < NN) {
            float* r = g_Y + (size_t)n0 * 512 + cb + tc * 8;
            ((float4*)r)[0] = make_float4(lo[0], lo[1], lo[2], lo[3]);
            ((float4*)r)[1] = make_float4(lo[4], lo[5], lo[6], lo[7]);
        }
        if (n0 + 1 < NN) {
            float* r = g_Y + (size_t)(n0 + 1) * 512 + cb + tc * 8;
            ((float4*)r)[0] = make_float4(hi[0], hi[1], hi[2], hi[3]);
            ((float4*)r)[1] = make_float4(hi[4], hi[5], hi[6], hi[7]);
        }
    }
}

// ---------------- stats1: per (graph, 64-ch chunk), gather from Y ----------------
__global__ void k_stats1g() {
    int g  = blockIdx.x >> 2;
    int c0 = (blockIdx.x & 3) * 64;
    int t = threadIdx.x;
    int c = c0 + (t & 63), lane = t >> 6;
    int s = g_off[g], eend = g_off[g + 1];
    float S = 0.f, Q = 0.f;
    for (int p = s + lane; p < eend; p += 4) {
        int nc = g_scol[p], nr = g_srow[p];
        float v = g_Y[nc * 512 + c] + g_Y[nr * 512 + 256 + c];
        S += v; Q += v * v;
    }
    __shared__ float sS[256], sQ[256];
    sS[t] = S; sQ[t] = Q;
    __syncthreads();
    if (t < 128) { sS[t] += sS[t + 128]; sQ[t] += sQ[t + 128]; }
    __syncthreads();
    if (t < 64) {
        float Ssum = sS[t] + sS[t + 64];
        float Qsum = sQ[t] + sQ[t + 64];
        float cnt = (float)max(eend - s, 1);
        float m = Ssum / cnt;
        float var = Qsum / cnt - m * m;
        float iv = rsqrtf(var + EPS_IN);
        g_inv1 [g * C1 + c0 + t] = iv;
        g_miv1 [g * C1 + c0 + t] = m * iv;
    }
}

// ---------------- GEMM2: fp16 2-term, double-buffered pipeline, M=64 tiles ----------------
// smem bytes: [0) B fp16 frags 33792 | stage s: hi at 33792+s*65536, lo at +32768.
__device__ __forceinline__ void gather64(char* cAhi, char* cAlo, int tile, int m, int q) {
    int pos = tile * 64 + m;
    int g = g_gid[pos];
    int nc = g_scol[pos], nr = g_srow[pos];
    const float4* yc = (const float4*)(g_Y + nc * 512) + q * 8;
    const float4* yr = (const float4*)(g_Y + nr * 512 + 256) + q * 8;
    const float4* vr = (const float4*)(g_inv1 + g * C1) + q * 8;
    const float4* mv = (const float4*)(g_miv1 + g * C1) + q * 8;
    int msw = m & 7;
    u32 hb0 = 0, hb1 = 0, lb0 = 0, lb1 = 0;
    #pragma unroll
    for (int jj = 0; jj < 8; jj++) {
        float4 a = yc[jj], b = yr[jj], iv = vr[jj], mm = mv[jj];
        float v0 = fmaxf(fmaf(a.x + b.x, iv.x, -mm.x), 0.f);
        float v1 = fmaxf(fmaf(a.y + b.y, iv.y, -mm.y), 0.f);
        float v2 = fmaxf(fmaf(a.z + b.z, iv.z, -mm.z), 0.f);
        float v3 = fmaxf(fmaf(a.w + b.w, iv.w, -mm.w), 0.f);
        u32 h0, l0, h1, l1;
        hsplit(v0, v1, h0, l0);
        hsplit(v2, v3, h1, l1);
        if ((jj & 1) == 0) { hb0 = h0; hb1 = h1; lb0 = l0; lb1 = l1; }
        else {
            int oct = q * 4 + (jj >> 1);
            int gran = m * 32 + (oct ^ msw);
            *(uint4*)(cAhi + gran * 16) = make_uint4(hb0, hb1, h0, h1);
            *(uint4*)(cAlo + gran * 16) = make_uint4(lb0, lb1, l0, l1);
        }
    }
}

__global__ __launch_bounds__(512, 1) void k_gemm2_mma()
{
    extern __shared__ u32 sm[];
    u32* sB = sm;
    char* smc = (char*)sm;

    int tid = threadIdx.x;
    for (int i = tid; i < 8192; i += 512) {
        int a = i >> 6, j = i & 63;
        sB[a * 66 + j] = g_B2h[i];
    }

    int w = tid >> 5, lane = tid & 31;
    int wm = w & 1, wn = w >> 1;        // M 32-slice (2), N 8-slice (8)
    int q = tid >> 6, m = tid & 63;     // producer: channel octet-quad, edge
    // ldmatrix lane geometry
    int lt = lane >> 3, lr = lane & 7;
    int lrow8 = (lt & 1) * 8 + lr;
    int lth = lt >> 1;

    int t0 = blockIdx.x * TPC;
    int tend = t0 + TPC;
    if (tend > NT2) tend = NT2;
    int n = tend - t0;

    if (n > 0)
        gather64(smc + 33792, smc + 33792 + 32768, t0, m, q);
    __syncthreads();

    for (int i = 0; i < n; i++) {
        char* cAhi = smc + 33792 + (i & 1) * 65536;
        char* cAlo = cAhi + 32768;
        u32 aAhi = smem_u32(cAhi);
        u32 aAlo = smem_u32(cAlo);

        if (i + 1 < n) {
            char* nAhi = smc + 33792 + ((i + 1) & 1) * 65536;
            gather64(nAhi, nAhi + 32768, t0 + i + 1, m, q);
        }

        float d[2][4];
        #pragma unroll
        for (int mi2 = 0; mi2 < 2; mi2++)
            #pragma unroll
            for (int r = 0; r < 4; r++) d[mi2][r] = 0.f;

        #pragma unroll
        for (int ki = 0; ki < 16; ki++) {
            u32 ah[2][4], al[2][4];
            #pragma unroll
            for (int mi2 = 0; mi2 < 2; mi2++) {
                int ml = wm * 32 + mi2 * 16 + lrow8;
                int oct = 2 * ki + lth;
                u32 goff = (u32)(ml * 32 + (oct ^ (ml & 7))) * 16;
                ldm_x4(ah[mi2], aAhi + goff);
                ldm_x4(al[mi2], aAlo + goff);
            }
            int batom = (wn * 16 + ki) * 66 + lane * 2;
            uint2 bv = *(const uint2*)(sB + batom);
            u32 bb[2] = {bv.x, bv.y};
            mma_f16(d[0], ah[0], bb);
            mma_f16(d[1], ah[1], bb);
            mma_f16(d[0], al[0], bb);
            mma_f16(d[1], al[1], bb);
        }
        {
            int r0base = (t0 + i) * 64 + wm * 32 + (lane >> 2);
            int cb = wn * 8 + (lane & 3) * 2;
            #pragma unroll
            for (int mi2 = 0; mi2 < 2; mi2++) {
                size_t rA = (size_t)(r0base + mi2 * 16);
                size_t rB = rA + 8;
                *(float2*)(g_x2 + rA * C2 + cb) = make_float2(d[mi2][0], d[mi2][1]);
                *(float2*)(g_x2 + rB * C2 + cb) = make_float2(d[mi2][2], d[mi2][3]);
            }
        }
        __syncthreads();
    }
}

// ---------------- stats2 ----------------
__global__ void k_stats2() {
    int g  = blockIdx.x >> 1;
    int c0 = (blockIdx.x & 1) * 32;
    int t = threadIdx.x;
    int c = c0 + (t & 31), r = t >> 5;
    int s = g_off[g], eend = g_off[g + 1];
    float S = 0.f, Q = 0.f;
    for (int p = s + r; p < eend; p += 8) {
        float v = g_x2[(size_t)p * C2 + c];
        S += v; Q += v * v;
    }
    __shared__ float sS[256], sQ[256];
    sS[t] = S; sQ[t] = Q;
    __syncthreads();
    for (int h2 = 128; h2 >= 32; h2 >>= 1) {
        if (t < h2) { sS[t] += sS[t + h2]; sQ[t] += sQ[t + h2]; }
        __syncthreads();
    }
    if (t < 32) {
        float cnt = (float)max(eend - s, 1);
        float m = sS[t] / cnt;
        float var = sQ[t] / cnt - m * m;
        float iv = rsqrtf(var + EPS_IN);
        g_inv2 [g * C2 + c0 + t] = iv;
        g_miv2 [g * C2 + c0 + t] = m * iv;
    }
}

// ---------------- final layer ----------------
__global__ void k_final(const float* __restrict__ W3, const float* __restrict__ b3,
                        float* __restrict__ out)
{
    __shared__ float sw[64];
    int tid = threadIdx.x;
    if (tid < 64) sw[tid] = W3[tid];
    __syncthreads();
    int pos = blockIdx.x * 128 + (tid >> 1);
    int half = tid & 1;
    float acc = 0.f;
    if (pos < E_EDGES) {
        int g = g_gid[pos];
        const float4* xr = (const float4*)g_x2    + (size_t)pos * 16 + half * 8;
        const float4* vr = (const float4*)g_inv2  + g * 16 + half * 8;
        const float4* mr = (const float4*)g_miv2  + g * 16 + half * 8;
        #pragma unroll
        for (int j = 0; j < 8; j++) {
            float4 x = xr[j], iv = vr[j], mv = mr[j];
            int k = half * 32 + j * 4;
            acc += fmaxf(fmaf(x.x, iv.x, -mv.x), 0.f) * sw[k]
                 + fmaxf(fmaf(x.y, iv.y, -mv.y), 0.f) * sw[k + 1]
                 + fmaxf(fmaf(x.z, iv.z, -mv.z), 0.f) * sw[k + 2]
                 + fmaxf(fmaf(x.w, iv.w, -mv.w), 0.f) * sw[k + 3];
        }
    }
    float other = __shfl_xor_sync(0xffffffffu, acc, 1);
    if (half == 0 && pos < E_EDGES) out[g_perm[pos]] = acc + other + b3[0];
}

// ---------------- launch ----------------
extern "C" void kernel_launch(void* const* d_in, const int* in_sizes, int n_in,
                              void* d_out, int out_size)
{
    const float* emb   = (const float*)d_in[0];
    const float* W1    = (const float*)d_in[1];
    const float* W2    = (const float*)d_in[3];
    const float* W3    = (const float*)d_in[5];
    const float* b3    = (const float*)d_in[6];
    const int*   ei    = (const int*)d_in[7];
    const int*   batch = (const int*)d_in[8];
    const int* col = ei;
    const int* row = ei + E_EDGES;
    float* out = (float*)d_out;

    static int attr_set = 0;
    if (!attr_set) {
        cudaFuncSetAttribute(k_gemm2_mma, cudaFuncAttributeMaxDynamicSharedMemorySize, 164864);
        attr_set = 1;
    }

    k_zero<<<1, 512>>>();
    k_hist<<<1024, 256>>>(col, batch);
    k_scan<<<1, 512>>>();
    k_emb<<<dim3((NN + 63) / 64, 4), 256>>>(emb, W1);   // launch idx 3 -> profiled
    k_scatter<<<(E_EDGES + 2047) / 2048, 256>>>(col, row, batch);
    k_prep2<<<16, 512>>>(W2);
    k_stats1g<<<NG * 4, 256>>>();
    k_gemm2_mma<<<PGRID, 512, 164864>>>();
    k_stats2<<<NG * 2, 256>>>();
    k_final<<<EP / 128, 256>>>(W3, b3, out);
}